// round 14
// baseline (speedup 1.0000x reference)
#include <cuda_runtime.h>
#include <cuda_bf16.h>
#include <cstdint>

// DeepRedModel_8589934783 — one CTA per batch element, 16 warps, 512 threads.
// Phase 2 uses 16x32 super-tiles: B cached for an n-PAIR (64 regs), each A
// fragment feeds 4 MMAs -> ~40% fewer LDSM wavefronts (smem pipe is the binder).
// I tile padded to 224 rows of zeros (tanh(0)=0 -> inert in all reductions).

#define B_BATCH 1024
#define S_LEN   200
#define D_DIM   128
#define ROWS_U  208             // 13 m-tiles
#define ROWS_I  224             // 14 n-tiles = 7 n-pairs
#define ROW_BYTES 272           // 17*16B; LDSM conflict-free (row stride 4 banks)
#define NMT     13
#define NNP     7               // n-pairs
#define NST     (NMT * NNP)     // 91 super-tiles
#define NWARPS  16
#define NTHREADS 512

// shared memory byte offsets
#define OFF_U    0                              // 208*272 = 56576
#define OFF_I    56576                          // 224*272 = 60928
#define OFF_USUM 117504                         // 128 f32
#define OFF_ISUM (OFF_USUM + 512)               // 118016
#define OFF_ICOL (OFF_ISUM + 512)               // 118528 : 224 f32 (atomic, rare)
#define OFF_UROW (OFF_ICOL + 896)               // 119424 : 208 f32 reduced row sums
#define OFF_UW   (OFF_UROW + 832)               // 120256 : 208 f32 user weights
#define OFF_IW   (OFF_UW + 832)                 // 121088 : item weights
#define OFF_WROW (OFF_IW + 832)                 // 121920 : 16 warps x 208 f32 scratch
                                                //          (reused as phase-4 partials)
#define SMEM_TOTAL (OFF_WROW + NWARPS * ROWS_U * 4)   // 135232 bytes

__device__ __forceinline__ float tanh_fast(float x) {
    float r;
    asm("tanh.approx.f32 %0, %1;" : "=f"(r) : "f"(x));
    return r;
}

__device__ __forceinline__ void mma16816(float c[4], const uint32_t a[4],
                                         uint32_t b0, uint32_t b1) {
    asm volatile(
        "mma.sync.aligned.m16n8k16.row.col.f32.bf16.bf16.f32 "
        "{%0,%1,%2,%3}, {%4,%5,%6,%7}, {%8,%9}, {%0,%1,%2,%3};\n"
        : "+f"(c[0]), "+f"(c[1]), "+f"(c[2]), "+f"(c[3])
        : "r"(a[0]), "r"(a[1]), "r"(a[2]), "r"(a[3]), "r"(b0), "r"(b1));
}

// Non-trans ldmatrix x4: addr row=(lane&15), k-block=(lane>>4)*16B delivers
// A fragment = (r0,r1,r2,r3); for row-major [n][k] tiles B = (b00,b10,b01,b11).
__device__ __forceinline__ void ldsm_x4(uint32_t r[4], uint32_t saddr) {
    asm volatile("ldmatrix.sync.aligned.m8n8.x4.shared.b16 {%0,%1,%2,%3}, [%4];"
                 : "=r"(r[0]), "=r"(r[1]), "=r"(r[2]), "=r"(r[3]) : "r"(saddr)
                 : "memory");
}

__global__ __launch_bounds__(NTHREADS, 1)
void deepred_kernel(const int* __restrict__ user_nh,
                    const float* __restrict__ user_mask,
                    const int* __restrict__ item_nh,
                    const float* __restrict__ item_mask,
                    const float* __restrict__ table,
                    float* __restrict__ out) {
    extern __shared__ char smem[];
    const int b    = blockIdx.x;
    const int tid  = threadIdx.x;
    const int wid  = tid >> 5;
    const int lane = tid & 31;

    // ---- zero all scratch past the tiles ----
    {
        float* z = (float*)(smem + OFF_USUM);
        const int nz = (SMEM_TOTAL - OFF_USUM) / 4;
        for (int i = tid; i < nz; i += NTHREADS) z[i] = 0.0f;
    }
    __syncthreads();

    // ---- phase 1: gather (fp32 -> bf16 smem, fp32 column sums), MLP<=14 ----
    #pragma unroll
    for (int which = 0; which < 2; ++which) {
        const int* nh = (which == 0 ? user_nh : item_nh) + b * S_LEN;
        char* dstBase = smem + (which == 0 ? OFF_U : OFF_I);
        float* csum = (float*)(smem + (which == 0 ? OFF_USUM : OFF_ISUM));
        const int rows = which ? ROWS_I : ROWS_U;

        float4 v[14];
        #pragma unroll
        for (int j = 0; j < 14; ++j) {
            int s = wid + j * NWARPS;
            float4 t = make_float4(0.f, 0.f, 0.f, 0.f);
            if (s < S_LEN) {
                int idx = __ldg(&nh[s]);
                if (idx != 0)                   // padding_idx=0 -> zero row
                    t = __ldg((const float4*)(table + (size_t)idx * D_DIM) + lane);
            }
            v[j] = t;
        }
        float ax = 0.f, ay = 0.f, az = 0.f, aw = 0.f;
        #pragma unroll
        for (int j = 0; j < 14; ++j) {
            int s = wid + j * NWARPS;
            if (s < rows) {                      // writes zeros for s in [200,rows)
                ax += v[j].x; ay += v[j].y; az += v[j].z; aw += v[j].w;
                __nv_bfloat162 h0 = __floats2bfloat162_rn(v[j].x, v[j].y);
                __nv_bfloat162 h1 = __floats2bfloat162_rn(v[j].z, v[j].w);
                uint2 packed = make_uint2(*(uint32_t*)&h0, *(uint32_t*)&h1);
                *(uint2*)(dstBase + s * ROW_BYTES + lane * 8) = packed;
            }
        }
        atomicAdd(&csum[lane * 4 + 0], ax);
        atomicAdd(&csum[lane * 4 + 1], ay);
        atomicAdd(&csum[lane * 4 + 2], az);
        atomicAdd(&csum[lane * 4 + 3], aw);
    }
    __syncthreads();

    // ---- phase 2: 16x32 super-tiled bf16 MMA; mt fast, n-pair fixed per run ----
    {
        float* icol = (float*)(smem + OFF_ICOL);
        float* wrow = (float*)(smem + OFF_WROW) + wid * ROWS_U;
        const int g  = lane >> 2;
        const int tq = lane & 3;

        const uint32_t ubase = (uint32_t)__cvta_generic_to_shared(smem + OFF_U);
        const uint32_t ibase = (uint32_t)__cvta_generic_to_shared(smem + OFF_I);
        const uint32_t lmoff = (uint32_t)(lane & 15) * ROW_BYTES + (uint32_t)(lane >> 4) * 16;

        // 91 super-tiles: warps 0-10 get 6, warps 11-15 get 5 (consecutive)
        int start = (wid < 11) ? wid * 6 : 66 + (wid - 11) * 5;
        int end   = start + ((wid < 11) ? 6 : 5);

        uint32_t Bv[16][4];                      // n-pair fragment cache (64 regs)
        int cur_np = -1;
        float cc[8] = {0.f,0.f,0.f,0.f,0.f,0.f,0.f,0.f};   // col accumulators

        for (int st = start; st < end; ++st) {
            int mt = st % NMT;
            int np = st / NMT;
            if (np != cur_np) {
                if (cur_np >= 0) {               // flush col sums for finished n-pair
                    #pragma unroll
                    for (int j = 0; j < 8; ++j) {
                        cc[j] += __shfl_xor_sync(0xffffffffu, cc[j], 4);
                        cc[j] += __shfl_xor_sync(0xffffffffu, cc[j], 8);
                        cc[j] += __shfl_xor_sync(0xffffffffu, cc[j], 16);
                    }
                    if (g == 0) {
                        int cb = cur_np * 32;
                        atomicAdd(&icol[cb + tq * 2],          cc[0]);
                        atomicAdd(&icol[cb + tq * 2 + 1],      cc[1]);
                        atomicAdd(&icol[cb + 8 + tq * 2],      cc[2]);
                        atomicAdd(&icol[cb + 9 + tq * 2],      cc[3]);
                        atomicAdd(&icol[cb + 16 + tq * 2],     cc[4]);
                        atomicAdd(&icol[cb + 17 + tq * 2],     cc[5]);
                        atomicAdd(&icol[cb + 24 + tq * 2],     cc[6]);
                        atomicAdd(&icol[cb + 25 + tq * 2],     cc[7]);
                    }
                    #pragma unroll
                    for (int j = 0; j < 8; ++j) cc[j] = 0.f;
                }
                cur_np = np;
                uint32_t bb0 = ibase + (uint32_t)(np * 32) * ROW_BYTES + lmoff;
                uint32_t bb1 = bb0 + 16u * ROW_BYTES;
                #pragma unroll
                for (int kk = 0; kk < 8; ++kk) {
                    ldsm_x4(Bv[kk],     bb0 + kk * 32);
                    ldsm_x4(Bv[8 + kk], bb1 + kk * 32);
                }
            }
            uint32_t abase = ubase + (uint32_t)(mt * 16) * ROW_BYTES + lmoff;

            float c[4][4] = {{0.f,0.f,0.f,0.f},{0.f,0.f,0.f,0.f},
                             {0.f,0.f,0.f,0.f},{0.f,0.f,0.f,0.f}};
            #pragma unroll
            for (int kk = 0; kk < 8; ++kk) {
                uint32_t Av[4];                  // transient A fragment -> 4 MMAs
                ldsm_x4(Av, abase + kk * 32);
                mma16816(c[0], Av, Bv[kk][0],     Bv[kk][2]);
                mma16816(c[1], Av, Bv[kk][1],     Bv[kk][3]);
                mma16816(c[2], Av, Bv[8 + kk][0], Bv[8 + kk][2]);
                mma16816(c[3], Av, Bv[8 + kk][1], Bv[8 + kk][3]);
            }
            // tanh in place
            #pragma unroll
            for (int j = 0; j < 4; ++j)
                #pragma unroll
                for (int q = 0; q < 4; ++q)
                    c[j][q] = tanh_fast(c[j][q]);

            // col partials (fixed n-pair): registers only
            cc[0] += c[0][0] + c[0][2];   // col np*32 + tq*2
            cc[1] += c[0][1] + c[0][3];   // +1
            cc[2] += c[1][0] + c[1][2];   // +8
            cc[3] += c[1][1] + c[1][3];   // +9
            cc[4] += c[2][0] + c[2][2];   // +16
            cc[5] += c[2][1] + c[2][3];   // +17
            cc[6] += c[3][0] + c[3][2];   // +24
            cc[7] += c[3][1] + c[3][3];   // +25

            // row sums over all 32 cols of this super-tile
            float rlow  = c[0][0] + c[0][1] + c[1][0] + c[1][1]
                        + c[2][0] + c[2][1] + c[3][0] + c[3][1];   // row mt*16+g
            float rhigh = c[0][2] + c[0][3] + c[1][2] + c[1][3]
                        + c[2][2] + c[2][3] + c[3][2] + c[3][3];   // row mt*16+g+8
            rlow  += __shfl_xor_sync(0xffffffffu, rlow, 1);
            rlow  += __shfl_xor_sync(0xffffffffu, rlow, 2);
            rhigh += __shfl_xor_sync(0xffffffffu, rhigh, 1);
            rhigh += __shfl_xor_sync(0xffffffffu, rhigh, 2);
            if (tq == 0) {
                wrow[mt * 16 + g]     += rlow;
                wrow[mt * 16 + g + 8] += rhigh;
            }
        }
        // final flush
        if (cur_np >= 0) {
            #pragma unroll
            for (int j = 0; j < 8; ++j) {
                cc[j] += __shfl_xor_sync(0xffffffffu, cc[j], 4);
                cc[j] += __shfl_xor_sync(0xffffffffu, cc[j], 8);
                cc[j] += __shfl_xor_sync(0xffffffffu, cc[j], 16);
            }
            if (g == 0) {
                int cb = cur_np * 32;
                atomicAdd(&icol[cb + tq * 2],          cc[0]);
                atomicAdd(&icol[cb + tq * 2 + 1],      cc[1]);
                atomicAdd(&icol[cb + 8 + tq * 2],      cc[2]);
                atomicAdd(&icol[cb + 9 + tq * 2],      cc[3]);
                atomicAdd(&icol[cb + 16 + tq * 2],     cc[4]);
                atomicAdd(&icol[cb + 17 + tq * 2],     cc[5]);
                atomicAdd(&icol[cb + 24 + tq * 2],     cc[6]);
                atomicAdd(&icol[cb + 25 + tq * 2],     cc[7]);
            }
        }
    }
    __syncthreads();

    // ---- phase 3a: parallel reduction of the 16 per-warp row-sum copies ----
    if (tid < ROWS_U) {
        const float* wrow = (const float*)(smem + OFF_WROW);
        float r = 0.f;
        #pragma unroll
        for (int ww = 0; ww < NWARPS; ++ww)
            r += wrow[ww * ROWS_U + tid];       // stride 208 words: conflict-free
        ((float*)(smem + OFF_UROW))[tid] = r;
    }
    __syncthreads();

    // ---- phase 3b: softmax over S (warp 0 = user, warp 1 = item) ----
    if (wid < 2) {
        const float* rowsum = (const float*)(smem + (wid == 0 ? OFF_UROW : OFF_ICOL));
        const float* mask = (wid == 0 ? user_mask : item_mask) + b * S_LEN;
        float* w = (float*)(smem + (wid == 0 ? OFF_UW : OFF_IW));
        float cv[7];
        float mx = -1e30f;
        #pragma unroll
        for (int i = 0; i < 7; ++i) {
            int s = lane + i * 32;
            float v = -1e30f;
            if (s < S_LEN) v = rowsum[s] * (1.0f / S_LEN) + mask[s];
            cv[i] = v;
            mx = fmaxf(mx, v);
        }
        #pragma unroll
        for (int m = 16; m >= 1; m >>= 1)
            mx = fmaxf(mx, __shfl_xor_sync(0xffffffffu, mx, m));
        float sum = 0.f;
        #pragma unroll
        for (int i = 0; i < 7; ++i) {
            int s = lane + i * 32;
            float e = 0.f;
            if (s < S_LEN) e = __expf(cv[i] - mx);
            cv[i] = e;
            sum += e;
        }
        #pragma unroll
        for (int m = 16; m >= 1; m >>= 1)
            sum += __shfl_xor_sync(0xffffffffu, sum, m);
        float inv = 1.0f / sum;
        #pragma unroll
        for (int i = 0; i < 7; ++i) {
            int s = lane + i * 32;
            if (s < S_LEN) w[s] = cv[i] * inv;
        }
    }
    __syncthreads();

    // ---- phase 4: rep = colsum/S + sum_s (w_s - 1/S) * bf16 row (vectorized) ----
    {
        const int side = wid >> 3;               // 8 warps user, 8 warps item
        const int wIn  = wid & 7;
        const char* mbase = smem + (side ? OFF_I : OFF_U);
        const float* w = (const float*)(smem + (side ? OFF_IW : OFF_UW));
        const int half = lane >> 4;              // two rows per warp iteration
        const int seg  = lane & 15;              // 16-byte segment within row

        float acc[8] = {0.f,0.f,0.f,0.f,0.f,0.f,0.f,0.f};
        for (int p = wIn; p < 100; p += 8) {
            int s = 2 * p + half;                // < 200
            float ws = w[s] - (1.0f / S_LEN);
            uint4 rv = *(const uint4*)(mbase + s * ROW_BYTES + seg * 16);
            const __nv_bfloat162* h2 = (const __nv_bfloat162*)&rv;
            #pragma unroll
            for (int q = 0; q < 4; ++q) {
                float2 f = __bfloat1622float2(h2[q]);
                acc[2 * q]     += ws * f.x;
                acc[2 * q + 1] += ws * f.y;
            }
        }
        #pragma unroll
        for (int j = 0; j < 8; ++j)
            acc[j] += __shfl_xor_sync(0xffffffffu, acc[j], 16);

        __syncthreads();                         // wrow reads done; reuse as partials
        float* part = (float*)(smem + OFF_WROW) + wid * 128;
        if (half == 0) {
            *(float4*)(part + seg * 8)     = make_float4(acc[0], acc[1], acc[2], acc[3]);
            *(float4*)(part + seg * 8 + 4) = make_float4(acc[4], acc[5], acc[6], acc[7]);
        }
        __syncthreads();

        if (tid < 256) {
            int oside = tid >> 7, d = tid & 127;
            const float* pb = (const float*)(smem + OFF_WROW) + oside * 8 * 128;
            float r = 0.f;
            #pragma unroll
            for (int ww = 0; ww < 8; ++ww)
                r += pb[ww * 128 + d];
            const float* csum = (const float*)(smem + (oside ? OFF_ISUM : OFF_USUM));
            float rep = csum[d] * (1.0f / S_LEN) + r;
            out[(size_t)oside * B_BATCH * D_DIM + (size_t)b * D_DIM + d] = rep;
        }
    }
}

extern "C" void kernel_launch(void* const* d_in, const int* in_sizes, int n_in,
                              void* d_out, int out_size) {
    // metadata order: users, user_nh, user_mask, items, item_nh, item_mask, emb_table
    const int*   user_nh   = (const int*)d_in[1];
    const float* user_mask = (const float*)d_in[2];
    const int*   item_nh   = (const int*)d_in[4];
    const float* item_mask = (const float*)d_in[5];
    const float* table     = (const float*)d_in[6];

    cudaFuncSetAttribute(deepred_kernel,
                         cudaFuncAttributeMaxDynamicSharedMemorySize, SMEM_TOTAL);
    deepred_kernel<<<B_BATCH, NTHREADS, SMEM_TOTAL>>>(
        user_nh, user_mask, item_nh, item_mask, table, (float*)d_out);
}